// round 11
// baseline (speedup 1.0000x reference)
#include <cuda_runtime.h>
#include <math.h>
#include <float.h>

#define H 2048
#define S 2048
#define V 50257

// ---------------- device scratch (allocation-free rule) ----------------
__device__ __align__(16) float g_part[64 * H];   // enc column-sum partials
__device__ __align__(16) float g_cat[2 * H];     // [embedded ; attn_applied]
__device__ __align__(16) float g_x[H];           // relu(comb output)
__device__ __align__(16) float g_gh[3 * H];      // w_hh @ h0 dots
__device__ __align__(16) float g_gx[3 * H];      // w_ih @ x dots
__device__ __align__(16) float g_h[H];           // h_new
__device__ __align__(16) float g_logits[V];
__device__ float g_shift;

__device__ __forceinline__ float warp_sum(float v) {
    #pragma unroll
    for (int o = 16; o > 0; o >>= 1) v += __shfl_xor_sync(0xffffffffu, v, o);
    return v;
}

// Single-row K=2048 dot (k6's proven shape): 2 phases of 8-deep batches.
__device__ __forceinline__ float dot2048_cs(const float4* __restrict__ wr,
                                            const float4* __restrict__ xs, int lane) {
    float acc = 0.f;
    #pragma unroll
    for (int ph = 0; ph < 2; ++ph) {
        float4 wb[8];
        #pragma unroll
        for (int i = 0; i < 8; ++i) wb[i] = __ldcs(wr + lane + 32 * (ph * 8 + i));
        #pragma unroll
        for (int i = 0; i < 8; ++i) {
            float4 x = xs[lane + 32 * (ph * 8 + i)];
            acc += wb[i].x * x.x + wb[i].y * x.y + wb[i].z * x.z + wb[i].w * x.w;
        }
    }
    return acc;
}

// PAIR dot: two adjacent K=512*PH rows, 16 loads in flight before consumption.
// Keeps per-warp DRAM demand continuous even at 1 pair per warp.
template <int PH>
__device__ __forceinline__ void dot_pair(const float4* __restrict__ w0,
                                         const float4* __restrict__ w1,
                                         const float4* __restrict__ xs, int lane,
                                         float& out0, float& out1) {
    float acc0 = 0.f, acc1 = 0.f;
    #pragma unroll
    for (int ph = 0; ph < PH; ++ph) {
        float4 a[8], c[8];
        #pragma unroll
        for (int i = 0; i < 8; ++i) a[i] = __ldcs(w0 + lane + 32 * (ph * 8 + i));
        #pragma unroll
        for (int i = 0; i < 8; ++i) c[i] = __ldcs(w1 + lane + 32 * (ph * 8 + i));
        #pragma unroll
        for (int i = 0; i < 8; ++i) {
            float4 x = xs[lane + 32 * (ph * 8 + i)];
            acc0 += a[i].x * x.x + a[i].y * x.y + a[i].z * x.z + a[i].w * x.w;
            acc1 += c[i].x * x.x + c[i].y * x.y + c[i].z * x.z + c[i].w * x.w;
        }
    }
    out0 = warp_sum(acc0);
    out1 = warp_sum(acc1);
}

// K1: fused independent work, 904 blocks x 256 thr:
//   [0, 384)   : gh = w_hh @ h0, PAIR-per-warp (3072 pairs = 384 blk x 8 warps)
//   [384, 896) : enc column-sum partials (8 col-chunks x 64 row-chunks of 32)
//   [896, 904) : embedding gather -> g_cat[0..H)
__global__ __launch_bounds__(256) void k1_fused(
        const float* __restrict__ w_hh, const float* __restrict__ hprev,
        const float* __restrict__ enc,  const float* __restrict__ emb,
        const int* __restrict__ input_id) {
    int b = blockIdx.x, tid = threadIdx.x;
    if (b < 384) {
        __shared__ __align__(16) float xs[H];
        ((float4*)xs)[tid]       = ((const float4*)hprev)[tid];
        ((float4*)xs)[tid + 256] = ((const float4*)hprev)[tid + 256];
        __syncthreads();
        int wpid = tid >> 5, lane = tid & 31;
        int pair = b * 8 + wpid;                     // 0..3071, exactly 1 per warp
        float d0, d1;
        dot_pair<2>((const float4*)(w_hh + (size_t)(2 * pair) * H),
                    (const float4*)(w_hh + (size_t)(2 * pair + 1) * H),
                    (const float4*)xs, lane, d0, d1);
        if (lane == 0) { g_gh[2 * pair] = d0; g_gh[2 * pair + 1] = d1; }
    } else if (b < 896) {
        int cb = b - 384;
        int col = (cb & 7) * 256 + tid;
        int r0  = (cb >> 3) * 32;
        float s = 0.f;
        #pragma unroll
        for (int i = 0; i < 32; ++i)
            s += enc[(size_t)(r0 + i) * H + col];
        g_part[(cb >> 3) * H + col] = s;
    } else {
        int j = (b - 896) * 256 + tid;               // 0..2047
        g_cat[j] = emb[(size_t)input_id[0] * H + j];
    }
}

// K2: finish column sums -> g_cat[H..2H)
__global__ void k2_finish_cat() {
    int j = blockIdx.x * 256 + threadIdx.x;
    float s = 0.f;
    #pragma unroll
    for (int c = 0; c < 64; ++c) s += g_part[c * H + j];
    g_cat[H + j] = s;
}

// K3: x = relu(comb_w @ cat + comb_b), K=4096. PAIR-per-warp (1024 pairs),
// grid 148 x 256, stride loop.
__global__ __launch_bounds__(256) void k3_comb(const float* __restrict__ w,
                                               const float* __restrict__ bias) {
    __shared__ __align__(16) float xs[2 * H];        // 16 KB
    int tid = threadIdx.x;
    #pragma unroll
    for (int i = 0; i < 4; ++i)
        ((float4*)xs)[tid + 256 * i] = ((const float4*)g_cat)[tid + 256 * i];
    __syncthreads();
    int wpid = tid >> 5, lane = tid & 31;
    for (int pair = wpid * 148 + blockIdx.x; pair < H / 2; pair += 1184) {
        float d0, d1;
        dot_pair<4>((const float4*)(w + (size_t)(2 * pair) * 2 * H),
                    (const float4*)(w + (size_t)(2 * pair + 1) * 2 * H),
                    (const float4*)xs, lane, d0, d1);
        if (lane == 0) {
            g_x[2 * pair]     = fmaxf(d0 + bias[2 * pair], 0.f);
            g_x[2 * pair + 1] = fmaxf(d1 + bias[2 * pair + 1], 0.f);
        }
    }
}

// K4: gx = w_ih @ x. PAIR-per-warp: 3072 pairs, grid 148 x 512 (2368 warps),
// stride loop; adjacent rows per warp keep footprint dense.
__global__ __launch_bounds__(512) void k4_wih(const float* __restrict__ w_ih) {
    __shared__ __align__(16) float xs[H];
    int tid = threadIdx.x;
    ((float4*)xs)[tid] = ((const float4*)g_x)[tid];  // 512 float4 exactly
    __syncthreads();
    int wpid = tid >> 5, lane = tid & 31;
    for (int pair = wpid * 148 + blockIdx.x; pair < 3 * H / 2; pair += 2368) {
        float d0, d1;
        dot_pair<2>((const float4*)(w_ih + (size_t)(2 * pair) * H),
                    (const float4*)(w_ih + (size_t)(2 * pair + 1) * H),
                    (const float4*)xs, lane, d0, d1);
        if (lane == 0) { g_gx[2 * pair] = d0; g_gx[2 * pair + 1] = d1; }
    }
}

// K5: elementwise GRU gates -> g_h. 8 blocks x 256.
__global__ void k5_gates(const float* __restrict__ b_ih, const float* __restrict__ b_hh,
                         const float* __restrict__ hprev) {
    int j = blockIdx.x * 256 + threadIdx.x;
    float pre_r = g_gx[j]     + b_ih[j]     + g_gh[j]     + b_hh[j];
    float pre_z = g_gx[H + j] + b_ih[H + j] + g_gh[H + j] + b_hh[H + j];
    float r = 1.f / (1.f + expf(-pre_r));
    float z = 1.f / (1.f + expf(-pre_z));
    float n = tanhf(g_gx[2 * H + j] + b_ih[2 * H + j]
                    + r * (g_gh[2 * H + j] + b_hh[2 * H + j]));
    g_h[j] = (1.f - z) * n + z * hprev[j];
}

// K6: logits = out_w @ h_new + out_b. UNCHANGED from R10 (measured winner):
// grid 148 x 1024, row = wpid*148 + b, stride 4736, single wave.
__global__ __launch_bounds__(1024) void k6_out(const float* __restrict__ w,
                                               const float* __restrict__ bias) {
    __shared__ __align__(16) float xs[H];
    int tid = threadIdx.x;
    ((float4*)xs)[tid % 512] = ((const float4*)g_h)[tid % 512];
    __syncthreads();
    int wpid = tid >> 5, lane = tid & 31;
    for (int row = wpid * 148 + blockIdx.x; row < V; row += 4736) {
        float d = warp_sum(dot2048_cs((const float4*)(w + (size_t)row * H),
                                      (const float4*)xs, lane));
        if (lane == 0) g_logits[row] = d + bias[row];
    }
}

// K7: single-block online logsumexp over g_logits -> g_shift.
__global__ void k7_lse() {
    __shared__ float sm[1024], ss[1024];
    int tid = threadIdx.x;
    float m = -FLT_MAX, s = 0.f;
    for (int i = tid; i < V; i += 1024) {
        float l = g_logits[i];
        float nm = fmaxf(m, l);
        s = s * expf(m - nm) + expf(l - nm);
        m = nm;
    }
    sm[tid] = m; ss[tid] = s;
    __syncthreads();
    for (int o = 512; o > 0; o >>= 1) {
        if (tid < o) {
            float m2 = sm[tid + o], s2 = ss[tid + o];
            float nm = fmaxf(sm[tid], m2);
            ss[tid] = ss[tid] * expf(sm[tid] - nm) + s2 * expf(m2 - nm);
            sm[tid] = nm;
        }
        __syncthreads();
    }
    if (tid == 0) g_shift = sm[0] + logf(ss[0]);
}

// K8: write outputs: log_probs (V) | h_new (H) | attn_weights=1 (S)
__global__ void k8_write(float* __restrict__ out, int out_size) {
    int i = blockIdx.x * 256 + threadIdx.x;
    if (i >= out_size) return;
    if (i < V)            out[i] = g_logits[i] - g_shift;
    else if (i < V + H)   out[i] = g_h[i - V];
    else                  out[i] = 1.0f;
}

extern "C" void kernel_launch(void* const* d_in, const int* in_sizes, int n_in,
                              void* d_out, int out_size) {
    const int*   input_id = (const int*)  d_in[0];
    const float* hidden   = (const float*)d_in[1];   // (1,1,H)
    const float* enc      = (const float*)d_in[2];   // (S,H)
    const float* emb      = (const float*)d_in[3];   // (V,H)
    // d_in[4], d_in[5]: attn_w / attn_b — provably dead (softmax over singleton)
    const float* comb_w   = (const float*)d_in[6];
    const float* comb_b   = (const float*)d_in[7];
    const float* w_ih     = (const float*)d_in[8];
    const float* w_hh     = (const float*)d_in[9];
    const float* b_ih     = (const float*)d_in[10];
    const float* b_hh     = (const float*)d_in[11];
    const float* out_w    = (const float*)d_in[12];
    const float* out_b    = (const float*)d_in[13];
    float* out = (float*)d_out;

    k1_fused<<<904, 256>>>(w_hh, hidden, enc, emb, input_id);
    k2_finish_cat<<<H / 256, 256>>>();
    k3_comb<<<148, 256>>>(comb_w, comb_b);
    k4_wih<<<148, 512>>>(w_ih);
    k5_gates<<<H / 256, 256>>>(b_ih, b_hh, hidden);
    k6_out<<<148, 1024>>>(out_w, out_b);
    k7_lse<<<1, 1024>>>();
    k8_write<<<(out_size + 255) / 256, 256>>>(out, out_size);
}

// round 12
// speedup vs baseline: 1.0527x; 1.0527x over previous
#include <cuda_runtime.h>
#include <math.h>
#include <float.h>

#define H 2048
#define S 2048
#define V 50257
#define GRID 148
#define TPB 1024

// ---------------- device scratch (allocation-free rule) ----------------
__device__ __align__(16) float g_partT[2048 * 40]; // [col][38 partials, pad 40]
__device__ __align__(16) float g_cat[2 * H];       // [embedded ; attn_applied]
__device__ __align__(16) float g_x[H];             // relu(comb output)
__device__ __align__(16) float g_gh[3 * H];        // w_hh @ h0 dots
__device__ __align__(16) float g_gx[3 * H];        // w_ih @ x dots
__device__ __align__(16) float g_h[H];             // h_new
__device__ __align__(16) float g_logits[V];
__device__ float g_shift;
__device__ int g_bar_cnt[8];                       // zero-init; monotonic across replays
__device__ int g_bar_flag[8];

__device__ __forceinline__ float warp_sum(float v) {
    #pragma unroll
    for (int o = 16; o > 0; o >>= 1) v += __shfl_xor_sync(0xffffffffu, v, o);
    return v;
}

// Grid-wide barrier (CG-style). Replay-safe: generation = old/GRID, no resets.
// Requires all GRID CTAs co-resident (grid=148 = 1 CTA/SM, single wave).
__device__ __forceinline__ void grid_bar(int i) {
    __syncthreads();
    if (threadIdx.x == 0) {
        __threadfence();
        int old = atomicAdd(&g_bar_cnt[i], 1);
        int gen = old / GRID;
        if ((old % GRID) == GRID - 1) {
            atomicExch(&g_bar_flag[i], gen + 1);
        } else {
            while (atomicAdd(&g_bar_flag[i], 0) <= gen) __nanosleep(64);
        }
        __threadfence();
    }
    __syncthreads();
}

// Single-row K=2048 dot (proven k6 shape): 2 phases of 8-deep __ldcs batches.
__device__ __forceinline__ float dot2048_cs(const float4* __restrict__ wr,
                                            const float4* __restrict__ xs, int lane) {
    float acc = 0.f;
    #pragma unroll
    for (int ph = 0; ph < 2; ++ph) {
        float4 wb[8];
        #pragma unroll
        for (int i = 0; i < 8; ++i) wb[i] = __ldcs(wr + lane + 32 * (ph * 8 + i));
        #pragma unroll
        for (int i = 0; i < 8; ++i) {
            float4 x = xs[lane + 32 * (ph * 8 + i)];
            acc += wb[i].x * x.x + wb[i].y * x.y + wb[i].z * x.z + wb[i].w * x.w;
        }
    }
    return acc;
}

// ===== Kernel A: fused k1..k5 (everything before the vocab GEMV) =====
// grid 148 x 1024, persistent single wave, phases separated by grid_bar.
__global__ __launch_bounds__(TPB, 1) void kA_fused(
        const float* __restrict__ w_hh,   const float* __restrict__ hprev,
        const float* __restrict__ enc,    const float* __restrict__ emb,
        const int*   __restrict__ input_id,
        const float* __restrict__ comb_w, const float* __restrict__ comb_b,
        const float* __restrict__ w_ih,
        const float* __restrict__ b_ih,   const float* __restrict__ b_hh) {
    __shared__ __align__(16) float smem[2 * H + 64];
    int b = blockIdx.x, tid = threadIdx.x;
    int wpid = tid >> 5, lane = tid & 31;

    // ---- P1: w_hh GEMV (CTAs 0..109)  ||  enc colsum + embed (CTAs 110..147)
    if (b < 110) {
        ((float4*)smem)[tid % 512] = ((const float4*)hprev)[tid % 512];
        __syncthreads();
        int gw = wpid * 110 + b;                       // 0..3519
        for (int row = gw; row < 3 * H; row += 3520) { // 1-2 rows/warp
            float d = warp_sum(dot2048_cs((const float4*)(w_hh + (size_t)row * H),
                                          (const float4*)smem, lane));
            if (lane == 0) g_gh[row] = d;
        }
    } else {
        int e = b - 110;                               // 0..37
        if (e < 2) {                                   // embed gather
            int j = e * 1024 + tid;
            g_cat[j] = emb[(size_t)input_id[0] * H + j];
        }
        int start = e * 53 + min(e, 34);               // 34x54 + 4x53 = 2048
        int cnt = 53 + (e < 34 ? 1 : 0);
        int c0 = tid, c1 = tid + 1024;
        float s0 = 0.f, s1 = 0.f, s2 = 0.f, s3 = 0.f;
        int i = 0;
        for (; i + 2 <= cnt; i += 2) {
            const float* r0 = enc + (size_t)(start + i) * H;
            const float* r1 = enc + (size_t)(start + i + 1) * H;
            s0 += r0[c0]; s1 += r0[c1];
            s2 += r1[c0]; s3 += r1[c1];
        }
        if (i < cnt) {
            const float* r0 = enc + (size_t)(start + i) * H;
            s0 += r0[c0]; s1 += r0[c1];
        }
        g_partT[(size_t)c0 * 40 + e] = s0 + s2;        // transposed partials
        g_partT[(size_t)c1 * 40 + e] = s1 + s3;
    }
    grid_bar(0);

    // ---- P2: finish cat (CTAs 0,1; contiguous 38-float reads per col)
    if (b < 2) {
        int col = b * 1024 + tid;
        const float* p = g_partT + (size_t)col * 40;
        float s0 = 0.f, s1 = 0.f, s2 = 0.f, s3 = 0.f;
        #pragma unroll
        for (int c = 0; c < 36; c += 4) {
            s0 += p[c]; s1 += p[c + 1]; s2 += p[c + 2]; s3 += p[c + 3];
        }
        s0 += p[36]; s1 += p[37];
        g_cat[H + col] = (s0 + s1) + (s2 + s3);
    }
    grid_bar(1);

    // ---- P3: x = relu(comb_w @ cat + comb_b). 2 warps/row K-split, 13-14 rows/CTA.
    {
        ((float4*)smem)[tid] = ((const float4*)g_cat)[tid];   // 4096 floats exact
        __syncthreads();
        float* part = smem + 2 * H;
        int start = b * 13 + min(b, 124);              // 124x14 + 24x13 = 2048
        int cnt = 13 + (b < 124 ? 1 : 0);
        int wpair = wpid >> 1, half = wpid & 1;
        if (wpair < cnt) {
            int row = start + wpair;
            float d = warp_sum(dot2048_cs(
                (const float4*)(comb_w + (size_t)row * 2 * H + (size_t)half * H),
                (const float4*)(smem + half * H), lane));
            if (lane == 0) part[wpid] = d;
        }
        __syncthreads();
        if (tid < cnt) {
            int r = start + tid;
            g_x[r] = fmaxf(part[2 * tid] + part[2 * tid + 1] + comb_b[r], 0.f);
        }
    }
    grid_bar(2);

    // ---- P4: gx = w_ih @ x. Proven gw-stride mapping (4736 warps, 1-2 rows).
    {
        ((float4*)smem)[tid % 512] = ((const float4*)g_x)[tid % 512];
        __syncthreads();
        int gw = wpid * GRID + b;                      // 0..4735
        for (int row = gw; row < 3 * H; row += 4736) {
            float d = warp_sum(dot2048_cs((const float4*)(w_ih + (size_t)row * H),
                                          (const float4*)smem, lane));
            if (lane == 0) g_gx[row] = d;
        }
    }
    grid_bar(3);

    // ---- P5: GRU gates -> g_h (CTAs 0,1)
    if (b < 2) {
        int j = b * 1024 + tid;
        float pre_r = g_gx[j]     + b_ih[j]     + g_gh[j]     + b_hh[j];
        float pre_z = g_gx[H + j] + b_ih[H + j] + g_gh[H + j] + b_hh[H + j];
        float r = 1.f / (1.f + expf(-pre_r));
        float z = 1.f / (1.f + expf(-pre_z));
        float n = tanhf(g_gx[2 * H + j] + b_ih[2 * H + j]
                        + r * (g_gh[2 * H + j] + b_hh[2 * H + j]));
        g_h[j] = (1.f - z) * n + z * hprev[j];
    }
}

// ===== K6: logits = out_w @ h_new + out_b. UNCHANGED from R10 winner. =====
__global__ __launch_bounds__(1024) void k6_out(const float* __restrict__ w,
                                               const float* __restrict__ bias) {
    __shared__ __align__(16) float xs[H];
    int tid = threadIdx.x;
    ((float4*)xs)[tid % 512] = ((const float4*)g_h)[tid % 512];
    __syncthreads();
    int wpid = tid >> 5, lane = tid & 31;
    for (int row = wpid * 148 + blockIdx.x; row < V; row += 4736) {
        float d = warp_sum(dot2048_cs((const float4*)(w + (size_t)row * H),
                                      (const float4*)xs, lane));
        if (lane == 0) g_logits[row] = d + bias[row];
    }
}

// K7: single-block online logsumexp over g_logits -> g_shift.
__global__ void k7_lse() {
    __shared__ float sm[1024], ss[1024];
    int tid = threadIdx.x;
    float m = -FLT_MAX, s = 0.f;
    for (int i = tid; i < V; i += 1024) {
        float l = g_logits[i];
        float nm = fmaxf(m, l);
        s = s * expf(m - nm) + expf(l - nm);
        m = nm;
    }
    sm[tid] = m; ss[tid] = s;
    __syncthreads();
    for (int o = 512; o > 0; o >>= 1) {
        if (tid < o) {
            float m2 = sm[tid + o], s2 = ss[tid + o];
            float nm = fmaxf(sm[tid], m2);
            ss[tid] = ss[tid] * expf(sm[tid] - nm) + s2 * expf(m2 - nm);
            sm[tid] = nm;
        }
        __syncthreads();
    }
    if (tid == 0) g_shift = sm[0] + logf(ss[0]);
}

// K8: write outputs: log_probs (V) | h_new (H) | attn_weights=1 (S)
__global__ void k8_write(float* __restrict__ out, int out_size) {
    int i = blockIdx.x * 256 + threadIdx.x;
    if (i >= out_size) return;
    if (i < V)            out[i] = g_logits[i] - g_shift;
    else if (i < V + H)   out[i] = g_h[i - V];
    else                  out[i] = 1.0f;
}

extern "C" void kernel_launch(void* const* d_in, const int* in_sizes, int n_in,
                              void* d_out, int out_size) {
    const int*   input_id = (const int*)  d_in[0];
    const float* hidden   = (const float*)d_in[1];   // (1,1,H)
    const float* enc      = (const float*)d_in[2];   // (S,H)
    const float* emb      = (const float*)d_in[3];   // (V,H)
    // d_in[4], d_in[5]: attn_w / attn_b — provably dead (softmax over singleton)
    const float* comb_w   = (const float*)d_in[6];
    const float* comb_b   = (const float*)d_in[7];
    const float* w_ih     = (const float*)d_in[8];
    const float* w_hh     = (const float*)d_in[9];
    const float* b_ih     = (const float*)d_in[10];
    const float* b_hh     = (const float*)d_in[11];
    const float* out_w    = (const float*)d_in[12];
    const float* out_b    = (const float*)d_in[13];
    float* out = (float*)d_out;

    kA_fused<<<GRID, TPB>>>(w_hh, hidden, enc, emb, input_id,
                            comb_w, comb_b, w_ih, b_ih, b_hh);
    k6_out<<<148, 1024>>>(out_w, out_b);
    k7_lse<<<1, 1024>>>();
    k8_write<<<(out_size + 255) / 256, 256>>>(out, out_size);
}

// round 13
// speedup vs baseline: 1.0932x; 1.0385x over previous
#include <cuda_runtime.h>
#include <math.h>
#include <float.h>

#define H 2048
#define S 2048
#define V 50257
#define GRID 148
#define TPB 1024
#define NTHR (GRID * TPB)

// ---------------- device scratch (allocation-free rule) ----------------
__device__ __align__(16) float g_partT[2048 * 40]; // [col][38 partials, pad 40]
__device__ __align__(16) float g_cat[2 * H];       // [embedded ; attn_applied]
__device__ __align__(16) float g_x[H];             // relu(comb output)
__device__ __align__(16) float g_gh[3 * H];        // w_hh @ h0 dots
__device__ __align__(16) float g_gx[3 * H];        // w_ih @ x dots
__device__ __align__(16) float g_h[H];             // h_new
__device__ __align__(16) float g_logits[V];
__device__ float g_pm[GRID], g_ps[GRID];           // per-CTA lse partials
__device__ float g_shift;
__device__ int g_bar_cnt[8];                       // zero-init; monotonic across replays
__device__ int g_bar_flag[8];

__device__ __forceinline__ float warp_sum(float v) {
    #pragma unroll
    for (int o = 16; o > 0; o >>= 1) v += __shfl_xor_sync(0xffffffffu, v, o);
    return v;
}

// Grid-wide barrier (CG-style). Replay-safe: generation = old/GRID, no resets.
// Requires all GRID CTAs co-resident (grid=148 = 1 CTA/SM, single wave).
__device__ __forceinline__ void grid_bar(int i) {
    __syncthreads();
    if (threadIdx.x == 0) {
        __threadfence();
        int old = atomicAdd(&g_bar_cnt[i], 1);
        int gen = old / GRID;
        if ((old % GRID) == GRID - 1) {
            atomicExch(&g_bar_flag[i], gen + 1);
        } else {
            while (atomicAdd(&g_bar_flag[i], 0) <= gen) __nanosleep(64);
        }
        __threadfence();
    }
    __syncthreads();
}

// Single-row K=2048 dot (proven k6 shape): 2 phases of 8-deep __ldcs batches.
__device__ __forceinline__ float dot2048_cs(const float4* __restrict__ wr,
                                            const float4* __restrict__ xs, int lane) {
    float acc = 0.f;
    #pragma unroll
    for (int ph = 0; ph < 2; ++ph) {
        float4 wb[8];
        #pragma unroll
        for (int i = 0; i < 8; ++i) wb[i] = __ldcs(wr + lane + 32 * (ph * 8 + i));
        #pragma unroll
        for (int i = 0; i < 8; ++i) {
            float4 x = xs[lane + 32 * (ph * 8 + i)];
            acc += wb[i].x * x.x + wb[i].y * x.y + wb[i].z * x.z + wb[i].w * x.w;
        }
    }
    return acc;
}

// ===== THE kernel: entire decoder step in ONE launch, grid 148 x 1024 =====
__global__ __launch_bounds__(TPB, 1) void kAll(
        const float* __restrict__ w_hh,   const float* __restrict__ hprev,
        const float* __restrict__ enc,    const float* __restrict__ emb,
        const int*   __restrict__ input_id,
        const float* __restrict__ comb_w, const float* __restrict__ comb_b,
        const float* __restrict__ w_ih,
        const float* __restrict__ b_ih,   const float* __restrict__ b_hh,
        const float* __restrict__ out_w,  const float* __restrict__ out_b,
        float* __restrict__ out, int out_size) {
    __shared__ __align__(16) float smem[2 * H + 64];
    int b = blockIdx.x, tid = threadIdx.x;
    int wpid = tid >> 5, lane = tid & 31;

    // ---- P1: w_hh GEMV (CTAs 0..109)  ||  enc colsum + embed (CTAs 110..147)
    if (b < 110) {
        ((float4*)smem)[tid % 512] = ((const float4*)hprev)[tid % 512];
        __syncthreads();
        int gw = wpid * 110 + b;                       // 0..3519
        for (int row = gw; row < 3 * H; row += 3520) { // 1-2 rows/warp
            float d = warp_sum(dot2048_cs((const float4*)(w_hh + (size_t)row * H),
                                          (const float4*)smem, lane));
            if (lane == 0) g_gh[row] = d;
        }
    } else {
        int e = b - 110;                               // 0..37
        if (e < 2) {                                   // embed gather
            int j = e * 1024 + tid;
            g_cat[j] = emb[(size_t)input_id[0] * H + j];
        }
        int start = e * 53 + min(e, 34);               // 34x54 + 4x53 = 2048
        int cnt = 53 + (e < 34 ? 1 : 0);
        int c0 = tid, c1 = tid + 1024;
        float s0 = 0.f, s1 = 0.f, s2 = 0.f, s3 = 0.f;
        int i = 0;
        for (; i + 2 <= cnt; i += 2) {
            const float* r0 = enc + (size_t)(start + i) * H;
            const float* r1 = enc + (size_t)(start + i + 1) * H;
            s0 += r0[c0]; s1 += r0[c1];
            s2 += r1[c0]; s3 += r1[c1];
        }
        if (i < cnt) {
            const float* r0 = enc + (size_t)(start + i) * H;
            s0 += r0[c0]; s1 += r0[c1];
        }
        g_partT[(size_t)c0 * 40 + e] = s0 + s2;        // transposed partials
        g_partT[(size_t)c1 * 40 + e] = s1 + s3;
    }
    grid_bar(0);

    // ---- P2: finish cat (CTAs 0,1; contiguous 38-float reads per col)
    if (b < 2) {
        int col = b * 1024 + tid;
        const float* p = g_partT + (size_t)col * 40;
        float s0 = 0.f, s1 = 0.f, s2 = 0.f, s3 = 0.f;
        #pragma unroll
        for (int c = 0; c < 36; c += 4) {
            s0 += p[c]; s1 += p[c + 1]; s2 += p[c + 2]; s3 += p[c + 3];
        }
        s0 += p[36]; s1 += p[37];
        g_cat[H + col] = (s0 + s1) + (s2 + s3);
    }
    grid_bar(1);

    // ---- P3: x = relu(comb_w @ cat + comb_b). 2 warps/row K-split, 13-14 rows/CTA.
    {
        ((float4*)smem)[tid] = ((const float4*)g_cat)[tid];   // 4096 floats exact
        __syncthreads();
        float* part = smem + 2 * H;
        int start = b * 13 + min(b, 124);              // 124x14 + 24x13 = 2048
        int cnt = 13 + (b < 124 ? 1 : 0);
        int wpair = wpid >> 1, half = wpid & 1;
        if (wpair < cnt) {
            int row = start + wpair;
            float d = warp_sum(dot2048_cs(
                (const float4*)(comb_w + (size_t)row * 2 * H + (size_t)half * H),
                (const float4*)(smem + half * H), lane));
            if (lane == 0) part[wpid] = d;
        }
        __syncthreads();
        if (tid < cnt) {
            int r = start + tid;
            g_x[r] = fmaxf(part[2 * tid] + part[2 * tid + 1] + comb_b[r], 0.f);
        }
    }
    grid_bar(2);

    // ---- P4: gx = w_ih @ x. Proven gw-stride mapping (4736 warps, 1-2 rows).
    {
        ((float4*)smem)[tid % 512] = ((const float4*)g_x)[tid % 512];
        __syncthreads();
        int gw = wpid * GRID + b;                      // 0..4735
        for (int row = gw; row < 3 * H; row += 4736) {
            float d = warp_sum(dot2048_cs((const float4*)(w_ih + (size_t)row * H),
                                          (const float4*)smem, lane));
            if (lane == 0) g_gx[row] = d;
        }
    }
    grid_bar(3);

    // ---- P5: GRU gates -> g_h (CTAs 0,1)
    if (b < 2) {
        int j = b * 1024 + tid;
        float pre_r = g_gx[j]     + b_ih[j]     + g_gh[j]     + b_hh[j];
        float pre_z = g_gx[H + j] + b_ih[H + j] + g_gh[H + j] + b_hh[H + j];
        float r = 1.f / (1.f + expf(-pre_r));
        float z = 1.f / (1.f + expf(-pre_z));
        float n = tanhf(g_gx[2 * H + j] + b_ih[2 * H + j]
                        + r * (g_gh[2 * H + j] + b_hh[2 * H + j]));
        g_h[j] = (1.f - z) * n + z * hprev[j];
    }
    grid_bar(4);

    // ---- P6: logits = out_w @ h_new + out_b. The R10 k6 winner, verbatim mapping.
    {
        ((float4*)smem)[tid % 512] = ((const float4*)g_h)[tid % 512];
        __syncthreads();
        for (int row = wpid * GRID + b; row < V; row += 4736) {
            float d = warp_sum(dot2048_cs((const float4*)(out_w + (size_t)row * H),
                                          (const float4*)smem, lane));
            if (lane == 0) g_logits[row] = d + out_b[row];
        }
    }
    grid_bar(5);

    // ---- P7: per-CTA lse partial over strided slice, then CTA 0 combines.
    {
        float* sm = smem;            // reuse: 1024 + 1024 floats
        float* ss = smem + 1024;
        float m = -FLT_MAX, s = 0.f;
        for (int i = b * TPB + tid; i < V; i += NTHR) { // 0 or 1 element/thread
            float l = g_logits[i];
            float nm = fmaxf(m, l);
            s = s * expf(m - nm) + expf(l - nm);
            m = nm;
        }
        sm[tid] = m; ss[tid] = s;
        __syncthreads();
        for (int o = 512; o > 0; o >>= 1) {
            if (tid < o) {
                float m2 = sm[tid + o], s2 = ss[tid + o];
                float nm = fmaxf(sm[tid], m2);
                ss[tid] = ss[tid] * expf(sm[tid] - nm) + s2 * expf(m2 - nm);
                sm[tid] = nm;
            }
            __syncthreads();
        }
        if (tid == 0) { g_pm[b] = sm[0]; g_ps[b] = ss[0]; }
    }
    grid_bar(6);

    if (b == 0 && tid < 32) {        // one warp combines 148 partials
        float m = -FLT_MAX, s = 0.f;
        #pragma unroll
        for (int c = 0; c < 5; ++c) {
            int idx = c * 32 + tid;
            if (idx < GRID) {
                float m2 = g_pm[idx], s2 = g_ps[idx];
                float nm = fmaxf(m, m2);
                s = s * expf(m - nm) + s2 * expf(m2 - nm);
                m = nm;
            }
        }
        #pragma unroll
        for (int o = 16; o > 0; o >>= 1) {
            float m2 = __shfl_xor_sync(0xffffffffu, m, o);
            float s2 = __shfl_xor_sync(0xffffffffu, s, o);
            float nm = fmaxf(m, m2);
            s = s * expf(m - nm) + s2 * expf(m2 - nm);
            m = nm;
        }
        if (tid == 0) g_shift = m + logf(s);
    }
    grid_bar(7);

    // ---- P8: write outputs: log_probs (V) | h_new (H) | attn_weights=1 (S)
    {
        float shift = g_shift;
        for (int i = b * TPB + tid; i < out_size; i += NTHR) {
            if (i < V)            out[i] = g_logits[i] - shift;
            else if (i < V + H)   out[i] = g_h[i - V];
            else                  out[i] = 1.0f;
        }
    }
}

extern "C" void kernel_launch(void* const* d_in, const int* in_sizes, int n_in,
                              void* d_out, int out_size) {
    const int*   input_id = (const int*)  d_in[0];
    const float* hidden   = (const float*)d_in[1];   // (1,1,H)
    const float* enc      = (const float*)d_in[2];   // (S,H)
    const float* emb      = (const float*)d_in[3];   // (V,H)
    // d_in[4], d_in[5]: attn_w / attn_b — provably dead (softmax over singleton)
    const float* comb_w   = (const float*)d_in[6];
    const float* comb_b   = (const float*)d_in[7];
    const float* w_ih     = (const float*)d_in[8];
    const float* w_hh     = (const float*)d_in[9];
    const float* b_ih     = (const float*)d_in[10];
    const float* b_hh     = (const float*)d_in[11];
    const float* out_w    = (const float*)d_in[12];
    const float* out_b    = (const float*)d_in[13];
    float* out = (float*)d_out;

    kAll<<<GRID, TPB>>>(w_hh, hidden, enc, emb, input_id,
                        comb_w, comb_b, w_ih, b_ih, b_hh,
                        out_w, out_b, out, out_size);
}